// round 3
// baseline (speedup 1.0000x reference)
#include <cuda_runtime.h>

#define C    85
#define SEQ  8192
#define NB   32
#define NCHK 8
#define CHL  1024
#define ISD  0.10846522890932808f  // 1/sqrt(85)

// ---------------- device scratch (no runtime allocation) ----------------
__device__ float g_Gpart[NB][NCHK][C * C];
__device__ float g_spart[NB][NCHK][C];
__device__ float g_M[NB][C * C];
__device__ float g_c[NB][C];

// packed fp32x2 FMA (Blackwell-native; 2x FFMA rate, PTX-only path)
__device__ __forceinline__ void ffma2(float2& d, float2 a, float2 b) {
    asm("fma.rn.f32x2 %0, %1, %2, %0;"
        : "+l"(reinterpret_cast<unsigned long long&>(d))
        : "l"(reinterpret_cast<unsigned long long&>(a)),
          "l"(reinterpret_cast<unsigned long long&>(b)));
}

// ============ kernel 1: Gram partials  G_part = Xc Xc^T, s_part = Xc 1 ============
// grid (NCHK, NB), 256 threads (16x16), 6x6 register tile over 96x96 (pad), f32x2 on l-pairs
__global__ __launch_bounds__(256, 2) void k_gram(const float* __restrict__ x) {
    const int b = blockIdx.y, ch = blockIdx.x;
    const int t = threadIdx.x, tx = t & 15, ty = t >> 4;
    __shared__ float Xs[96 * 66];  // 96 rows x 64 l, stride 66

    float2 acc[6][6];
#pragma unroll
    for (int u = 0; u < 6; u++)
#pragma unroll
        for (int v = 0; v < 6; v++) acc[u][v] = make_float2(0.f, 0.f);
    float srow = 0.f;

    const float* xb = x + (size_t)b * C * SEQ + ch * CHL;

    for (int st = 0; st < 16; ++st) {  // 16 stages x 64 l = 1024
#pragma unroll
        for (int i = 0; i < 6; i++) {
            int idx = t + i * 256;  // 0..1535 = 96 rows x 16 float4
            int r = idx >> 4, q = idx & 15;
            float4 v4 = make_float4(0.f, 0.f, 0.f, 0.f);
            if (r < C) v4 = *(const float4*)(xb + (size_t)r * SEQ + st * 64 + q * 4);
            float* d = &Xs[r * 66 + q * 4];
            d[0] = v4.x; d[1] = v4.y; d[2] = v4.z; d[3] = v4.w;
        }
        __syncthreads();

#pragma unroll
        for (int lp = 0; lp < 32; ++lp) {
            float2 af[6], bf[6];
#pragma unroll
            for (int u = 0; u < 6; u++) af[u] = *(const float2*)&Xs[(ty + 16 * u) * 66 + 2 * lp];
#pragma unroll
            for (int v = 0; v < 6; v++) bf[v] = *(const float2*)&Xs[(tx + 16 * v) * 66 + 2 * lp];
#pragma unroll
            for (int u = 0; u < 6; u++)
#pragma unroll
                for (int v = 0; v < 6; v++) ffma2(acc[u][v], af[u], bf[v]);
        }
        if (t < C) {
            float ssum = 0.f;
#pragma unroll
            for (int q = 0; q < 64; q++) ssum += Xs[t * 66 + q];
            srow += ssum;
        }
        __syncthreads();
    }

#pragma unroll
    for (int u = 0; u < 6; u++) {
        int i = ty + 16 * u;
        if (i >= C) continue;
#pragma unroll
        for (int v = 0; v < 6; v++) {
            int j = tx + 16 * v;
            if (j < C) g_Gpart[b][ch][i * C + j] = acc[u][v].x + acc[u][v].y;
        }
    }
    if (t < C) g_spart[b][ch][t] = srow;
}

// ============ kernel 2 (fused middle): reduce -> G,s ; H = Wq G ; S + softmax -> P ;
//              M = P Wv -> gmem ; c = P bv -> gmem.  grid (NB), 256 threads, dynamic smem.
__global__ void k_mid(const float* __restrict__ Wq, const float* __restrict__ Wk,
                      const float* __restrict__ Wv, const float* __restrict__ bq,
                      const float* __restrict__ bk, const float* __restrict__ bv) {
    extern __shared__ float sm[];
    float* Gs = sm;            // 85 x 86 (G, later reused for P)
    float* Hs = sm + 7310;     // 85 x 86
    float* Ws = sm + 14620;    // 85 x 87 (current weight matrix)
    __shared__ float ss[C], us[C], vs[C];
    const int b = blockIdx.x, t = threadIdx.x;

    for (int i = t; i < C * C; i += 256) Ws[(i / C) * 87 + (i % C)] = Wq[i];
    for (int i = t; i < C * C; i += 256) {
        float a = 0.f;
#pragma unroll
        for (int k = 0; k < NCHK; k++) a += g_Gpart[b][k][i];
        Gs[(i / C) * 86 + (i % C)] = a;
    }
    if (t < C) {
        float a = 0.f;
#pragma unroll
        for (int k = 0; k < NCHK; k++) a += g_spart[b][k][t];
        ss[t] = a;
    }
    __syncthreads();

    if (t < C) {  // u = Wq s
        float a = 0.f;
        for (int e = 0; e < C; e++) a += Ws[t * 87 + e] * ss[e];
        us[t] = a;
    }
    // H = Wq G
    for (int i = t; i < C * C; i += 256) {
        int r = i / C, j = i % C;
        float a = 0.f;
        for (int e = 0; e < C; e++) a += Ws[r * 87 + e] * Gs[e * 86 + j];
        Hs[r * 86 + j] = a;
    }
    __syncthreads();

    for (int i = t; i < C * C; i += 256) Ws[(i / C) * 87 + (i % C)] = Wk[i];
    __syncthreads();
    if (t < C) {  // v = Wk s
        float a = 0.f;
        for (int e = 0; e < C; e++) a += Ws[t * 87 + e] * ss[e];
        vs[t] = a;
    }
    __syncthreads();

    // S rows + softmax -> P (into Gs), c = P bv
    const int warp = t >> 5, lane = t & 31;
    const int d0 = lane, d1 = lane + 32, d2 = lane + 64;
    for (int c = warp; c < C; c += 8) {
        float s0 = 0.f, s1 = 0.f, s2 = 0.f;
        for (int e = 0; e < C; e++) {
            float h = Hs[c * 86 + e];
            s0 += h * Ws[d0 * 87 + e];
            s1 += h * Ws[d1 * 87 + e];
            if (d2 < C) s2 += h * Ws[d2 * 87 + e];
        }
        float uc = us[c], bqc = bq[c];
        s0 = (s0 + uc * bk[d0] + bqc * (vs[d0] + (float)SEQ * bk[d0])) * ISD;
        s1 = (s1 + uc * bk[d1] + bqc * (vs[d1] + (float)SEQ * bk[d1])) * ISD;
        s2 = (d2 < C) ? (s2 + uc * bk[d2] + bqc * (vs[d2] + (float)SEQ * bk[d2])) * ISD : -1e30f;
        float m = fmaxf(s0, fmaxf(s1, s2));
#pragma unroll
        for (int o = 16; o > 0; o >>= 1) m = fmaxf(m, __shfl_xor_sync(0xffffffffu, m, o));
        float e0 = __expf(s0 - m), e1 = __expf(s1 - m), e2 = (d2 < C) ? __expf(s2 - m) : 0.f;
        float sum = e0 + e1 + e2;
#pragma unroll
        for (int o = 16; o > 0; o >>= 1) sum += __shfl_xor_sync(0xffffffffu, sum, o);
        float inv = 1.f / sum;
        e0 *= inv; e1 *= inv; e2 *= inv;
        Gs[c * 86 + d0] = e0;
        Gs[c * 86 + d1] = e1;
        if (d2 < C) Gs[c * 86 + d2] = e2;
        float cv = e0 * bv[d0] + e1 * bv[d1] + ((d2 < C) ? e2 * bv[d2] : 0.f);
#pragma unroll
        for (int o = 16; o > 0; o >>= 1) cv += __shfl_xor_sync(0xffffffffu, cv, o);
        if (lane == 0) g_c[b][c] = cv;
    }
    __syncthreads();

    for (int i = t; i < C * C; i += 256) Ws[(i / C) * 87 + (i % C)] = Wv[i];
    __syncthreads();
    // M = P Wv
    for (int i = t; i < C * C; i += 256) {
        int r = i / C, f = i % C;
        float a = 0.f;
        for (int e = 0; e < C; e++) a += Gs[r * 86 + e] * Ws[e * 87 + f];
        g_M[b][i] = a;
    }
}

// ============ kernel 3: out = M X + c 1^T ============
// grid (64 L-tiles of 128, NB), 256 threads (16x16), 6 rows x 4 f32x2-cols per thread
__global__ __launch_bounds__(256, 2) void k_out(const float* __restrict__ x,
                                                float* __restrict__ out) {
    const int b = blockIdx.y, tile = blockIdx.x;
    const int t = threadIdx.x, tx = t & 15, ty = t >> 4;
    __shared__ float Ms[96 * C];   // [row 96][a 85], rows >= 85 zero
    __shared__ float cs[96];
    __shared__ float Xs[17 * 130];

    for (int i = t; i < 96 * C; i += 256) Ms[i] = (i < C * C) ? g_M[b][i] : 0.f;
    if (t < 96) cs[t] = (t < C) ? g_c[b][t] : 0.f;

    float2 acc[6][4];
#pragma unroll
    for (int u = 0; u < 6; u++)
#pragma unroll
        for (int v = 0; v < 4; v++) acc[u][v] = make_float2(0.f, 0.f);

    const float* xb = x + (size_t)b * C * SEQ + tile * 128;
    __syncthreads();

    for (int st = 0; st < 5; ++st) {  // 5 stages x 17 a-rows = 85
        const int a0 = st * 17;
        for (int i = t; i < 544; i += 256) {  // 17 rows x 32 float4
            int r = i >> 5, q = i & 31;
            float4 v4 = *(const float4*)(xb + (size_t)(a0 + r) * SEQ + q * 4);
            float* d = &Xs[r * 130 + q * 4];
            d[0] = v4.x; d[1] = v4.y; d[2] = v4.z; d[3] = v4.w;
        }
        __syncthreads();
#pragma unroll
        for (int a = 0; a < 17; ++a) {
            float2 bf[4];
#pragma unroll
            for (int v = 0; v < 4; v++) bf[v] = *(const float2*)&Xs[a * 130 + 2 * (tx + 16 * v)];
#pragma unroll
            for (int u = 0; u < 6; u++) {
                float mv = Ms[(ty + 16 * u) * C + a0 + a];
                float2 m2 = make_float2(mv, mv);
#pragma unroll
                for (int v = 0; v < 4; v++) ffma2(acc[u][v], m2, bf[v]);
            }
        }
        __syncthreads();
    }

#pragma unroll
    for (int u = 0; u < 6; u++) {
        int row = ty + 16 * u;
        if (row >= C) continue;
        float cv = cs[row];
        float* op = out + (size_t)b * C * SEQ + (size_t)row * SEQ + tile * 128;
#pragma unroll
        for (int v = 0; v < 4; v++) {
            int j = 2 * (tx + 16 * v);
            *(float2*)(op + j) = make_float2(acc[u][v].x + cv, acc[u][v].y + cv);
        }
    }
}

extern "C" void kernel_launch(void* const* d_in, const int* in_sizes, int n_in,
                              void* d_out, int out_size) {
    const float* x  = (const float*)d_in[0];
    const float* Wq = (const float*)d_in[1];
    const float* bq = (const float*)d_in[2];
    const float* Wk = (const float*)d_in[3];
    const float* bk = (const float*)d_in[4];
    const float* Wv = (const float*)d_in[5];
    const float* bv = (const float*)d_in[6];
    float* out = (float*)d_out;

    static bool attr_done = false;
    if (!attr_done) {
        cudaFuncSetAttribute(k_mid, cudaFuncAttributeMaxDynamicSharedMemorySize, 90112);
        attr_done = true;
    }

    k_gram<<<dim3(NCHK, NB), 256>>>(x);
    k_mid<<<NB, 256, 22015 * sizeof(float)>>>(Wq, Wk, Wv, bq, bk, bv);
    k_out<<<dim3(64, NB), 256>>>(x, out);
}

// round 6
// speedup vs baseline: 1.7924x; 1.7924x over previous
#include <cuda_runtime.h>
#include <cuda_bf16.h>
#include <cstdint>

#define C    85
#define SEQ  8192
#define NB   32
#define KCHK 4
#define KLEN 2048
#define ISD  0.10846522890932808f  // 1/sqrt(85)

// ---------------- device scratch ----------------
__device__ float g_hh[NB][KCHK][96 * 96];
__device__ float g_lh[NB][KCHK][96 * 96];
__device__ float g_spart[NB][KCHK][96];
__device__ __nv_bfloat16 g_Mhi[NB][96 * 96];
__device__ __nv_bfloat16 g_Mlo[NB][96 * 96];
__device__ float g_c[NB][C];

// ---------------- helpers ----------------
__device__ __forceinline__ uint32_t smem_u32(const void* p) {
    uint32_t a;
    asm("{ .reg .u64 t; cvta.to.shared.u64 t, %1; cvt.u32.u64 %0, t; }" : "=r"(a) : "l"(p));
    return a;
}
__device__ __forceinline__ void ldsm4(uint32_t& r0, uint32_t& r1, uint32_t& r2, uint32_t& r3,
                                      uint32_t addr) {
    asm volatile("ldmatrix.sync.aligned.m8n8.x4.shared.b16 {%0,%1,%2,%3}, [%4];"
                 : "=r"(r0), "=r"(r1), "=r"(r2), "=r"(r3) : "r"(addr));
}
__device__ __forceinline__ void ldsm4t(uint32_t& r0, uint32_t& r1, uint32_t& r2, uint32_t& r3,
                                       uint32_t addr) {
    asm volatile("ldmatrix.sync.aligned.m8n8.x4.trans.shared.b16 {%0,%1,%2,%3}, [%4];"
                 : "=r"(r0), "=r"(r1), "=r"(r2), "=r"(r3) : "r"(addr));
}
__device__ __forceinline__ void mma_bf16(float* d, const uint32_t* a, uint32_t b0, uint32_t b1) {
    asm volatile(
        "mma.sync.aligned.m16n8k16.row.col.f32.bf16.bf16.f32 "
        "{%0,%1,%2,%3},{%4,%5,%6,%7},{%8,%9},{%0,%1,%2,%3};"
        : "+f"(d[0]), "+f"(d[1]), "+f"(d[2]), "+f"(d[3])
        : "r"(a[0]), "r"(a[1]), "r"(a[2]), "r"(a[3]), "r"(b0), "r"(b1));
}

// ============ kernel 1: HMMA Gram partials ============
// grid (KCHK, NB), 256 thr. Stacked A = [Xhi;Xlo] (192 x K), B = Xhi^T.
// hh = Xhi Xhi^T, lh = Xlo Xhi^T accumulated in registers over K=2048.
__global__ __launch_bounds__(256, 1) void k_gram(const float* __restrict__ x) {
    __shared__ __align__(128) uint8_t s_hi[96 * 128];
    __shared__ __align__(128) uint8_t s_lo[96 * 128];
    __shared__ float s_red[1536];
    const int b = blockIdx.y, kc = blockIdx.x;
    const int t = threadIdx.x, lane = t & 31, wid = t >> 5;
    const int q = t & 15, rst = t >> 4;  // staging: rows rst+16i, float4 col q
    const float* xb = x + (size_t)b * C * SEQ + (size_t)kc * KLEN;

    const uint32_t a_hi = smem_u32(s_hi), a_lo = smem_u32(s_lo);
    const int wr = wid >> 1, wc = wid & 1;
    const uint32_t a_A = (wr < 2) ? a_hi : a_lo;
    const int m0 = (wr & 1) * 48, n0 = wc * 48;

    float acc[3][6][4];
#pragma unroll
    for (int mt = 0; mt < 3; mt++)
#pragma unroll
        for (int nt = 0; nt < 6; nt++)
#pragma unroll
            for (int e = 0; e < 4; e++) acc[mt][nt][e] = 0.f;

    float4 v[6];
    float srow[6] = {0.f, 0.f, 0.f, 0.f, 0.f, 0.f};
#pragma unroll
    for (int i = 0; i < 6; i++) {
        const int r = rst + 16 * i;
        if (r < C) v[i] = *(const float4*)(xb + (size_t)r * SEQ + q * 4);
    }

    for (int s = 0; s < 32; ++s) {
        __syncthreads();
#pragma unroll
        for (int i = 0; i < 6; i++) {
            const int r = rst + 16 * i;
            if (r < C) {
                const float4 w = v[i];
                __nv_bfloat162 h01 = __floats2bfloat162_rn(w.x, w.y);
                __nv_bfloat162 h23 = __floats2bfloat162_rn(w.z, w.w);
                float2 f01 = __bfloat1622float2(h01);
                float2 f23 = __bfloat1622float2(h23);
                __nv_bfloat162 l01 = __floats2bfloat162_rn(w.x - f01.x, w.y - f01.y);
                __nv_bfloat162 l23 = __floats2bfloat162_rn(w.z - f23.x, w.w - f23.y);
                const uint32_t cb = (uint32_t)(q * 8) ^ (uint32_t)((r & 7) << 4);
                *(uint2*)(s_hi + r * 128 + cb) =
                    make_uint2(*(uint32_t*)&h01, *(uint32_t*)&h23);
                *(uint2*)(s_lo + r * 128 + cb) =
                    make_uint2(*(uint32_t*)&l01, *(uint32_t*)&l23);
                srow[i] += (w.x + w.y) + (w.z + w.w);
            }
        }
        __syncthreads();
        if (s < 31) {
#pragma unroll
            for (int i = 0; i < 6; i++) {
                const int r = rst + 16 * i;
                if (r < C) v[i] = *(const float4*)(xb + (size_t)r * SEQ + (s + 1) * 64 + q * 4);
            }
        }
#pragma unroll
        for (int k = 0; k < 4; ++k) {
            uint32_t a[3][4], bb[3][4];
            const uint32_t cbA = 32 * k + ((lane & 16) ? 16 : 0);
#pragma unroll
            for (int mt = 0; mt < 3; mt++) {
                const int row = m0 + mt * 16 + (lane & 15);
                const uint32_t cb = cbA ^ ((row & 7) << 4);
                ldsm4(a[mt][0], a[mt][1], a[mt][2], a[mt][3], a_A + row * 128 + cb);
            }
            const uint32_t cbB = 32 * k + ((lane & 8) ? 16 : 0);
#pragma unroll
            for (int np = 0; np < 3; np++) {
                const int row = n0 + np * 16 + (lane & 7) + ((lane & 16) ? 8 : 0);
                const uint32_t cb = cbB ^ ((row & 7) << 4);
                ldsm4(bb[np][0], bb[np][1], bb[np][2], bb[np][3], a_hi + row * 128 + cb);
            }
#pragma unroll
            for (int mt = 0; mt < 3; mt++)
#pragma unroll
                for (int nt = 0; nt < 6; nt++) {
                    const int np = nt >> 1;
                    mma_bf16(acc[mt][nt], a[mt],
                             (nt & 1) ? bb[np][2] : bb[np][0],
                             (nt & 1) ? bb[np][3] : bb[np][1]);
                }
        }
    }

    float* base = (wr < 2) ? g_hh[b][kc] : g_lh[b][kc];
    const int rb = (wr & 1) * 48;
#pragma unroll
    for (int mt = 0; mt < 3; mt++) {
        const int row = rb + mt * 16 + (lane >> 2);
#pragma unroll
        for (int nt = 0; nt < 6; nt++) {
            const int col = n0 + nt * 8 + (lane & 3) * 2;
            *(float2*)&base[row * 96 + col] = make_float2(acc[mt][nt][0], acc[mt][nt][1]);
            *(float2*)&base[(row + 8) * 96 + col] = make_float2(acc[mt][nt][2], acc[mt][nt][3]);
        }
    }
#pragma unroll
    for (int i = 0; i < 6; i++) s_red[(rst + 16 * i) * 16 + q] = srow[i];
    __syncthreads();
    if (t < 96) {
        float a = 0.f;
#pragma unroll
        for (int qq = 0; qq < 16; qq++) a += s_red[t * 16 + qq];
        g_spart[b][kc][t] = a;
    }
}

// ============ kernel 2 (fused middle): G,s -> softmax -> M (bf16 split), c ============
__global__ void k_mid(const float* __restrict__ Wq, const float* __restrict__ Wk,
                      const float* __restrict__ Wv, const float* __restrict__ bq,
                      const float* __restrict__ bk, const float* __restrict__ bv) {
    extern __shared__ float sm[];
    float* Gs = sm;            // 85 x 86 (G, later P)
    float* Hs = sm + 7310;     // 85 x 86
    float* Ws = sm + 14620;    // 85 x 87
    __shared__ float ss[C], us[C], vs[C];
    const int b = blockIdx.x, t = threadIdx.x;

    for (int i = t; i < C * C; i += 256) Ws[(i / C) * 87 + (i % C)] = Wq[i];
    for (int i = t; i < C * C; i += 256) {
        const int r = i / C, cc = i % C;
        float a = 0.f;
#pragma unroll
        for (int k = 0; k < KCHK; k++)
            a += g_hh[b][k][r * 96 + cc] + g_lh[b][k][r * 96 + cc] + g_lh[b][k][cc * 96 + r];
        Gs[r * 86 + cc] = a;
    }
    if (t < C) {
        float a = 0.f;
#pragma unroll
        for (int k = 0; k < KCHK; k++) a += g_spart[b][k][t];
        ss[t] = a;
    }
    __syncthreads();

    if (t < C) {
        float a = 0.f;
        for (int e = 0; e < C; e++) a += Ws[t * 87 + e] * ss[e];
        us[t] = a;
    }
    for (int i = t; i < C * C; i += 256) {
        const int r = i / C, j = i % C;
        float a = 0.f;
        for (int e = 0; e < C; e++) a += Ws[r * 87 + e] * Gs[e * 86 + j];
        Hs[r * 86 + j] = a;
    }
    __syncthreads();

    for (int i = t; i < C * C; i += 256) Ws[(i / C) * 87 + (i % C)] = Wk[i];
    __syncthreads();
    if (t < C) {
        float a = 0.f;
        for (int e = 0; e < C; e++) a += Ws[t * 87 + e] * ss[e];
        vs[t] = a;
    }
    __syncthreads();

    const int warp = t >> 5, lane = t & 31;
    const int d0 = lane, d1 = lane + 32, d2 = lane + 64;
    for (int c = warp; c < C; c += 8) {
        float s0 = 0.f, s1 = 0.f, s2 = 0.f;
        for (int e = 0; e < C; e++) {
            const float h = Hs[c * 86 + e];
            s0 += h * Ws[d0 * 87 + e];
            s1 += h * Ws[d1 * 87 + e];
            if (d2 < C) s2 += h * Ws[d2 * 87 + e];
        }
        const float uc = us[c], bqc = bq[c];
        s0 = (s0 + uc * bk[d0] + bqc * (vs[d0] + (float)SEQ * bk[d0])) * ISD;
        s1 = (s1 + uc * bk[d1] + bqc * (vs[d1] + (float)SEQ * bk[d1])) * ISD;
        s2 = (d2 < C) ? (s2 + uc * bk[d2] + bqc * (vs[d2] + (float)SEQ * bk[d2])) * ISD : -1e30f;
        float m = fmaxf(s0, fmaxf(s1, s2));
#pragma unroll
        for (int o = 16; o > 0; o >>= 1) m = fmaxf(m, __shfl_xor_sync(0xffffffffu, m, o));
        float e0 = __expf(s0 - m), e1 = __expf(s1 - m), e2 = (d2 < C) ? __expf(s2 - m) : 0.f;
        float sum = e0 + e1 + e2;
#pragma unroll
        for (int o = 16; o > 0; o >>= 1) sum += __shfl_xor_sync(0xffffffffu, sum, o);
        const float inv = 1.f / sum;
        e0 *= inv; e1 *= inv; e2 *= inv;
        Gs[c * 86 + d0] = e0;
        Gs[c * 86 + d1] = e1;
        if (d2 < C) Gs[c * 86 + d2] = e2;
        float cv = e0 * bv[d0] + e1 * bv[d1] + ((d2 < C) ? e2 * bv[d2] : 0.f);
#pragma unroll
        for (int o = 16; o > 0; o >>= 1) cv += __shfl_xor_sync(0xffffffffu, cv, o);
        if (lane == 0) g_c[b][c] = cv;
    }
    __syncthreads();

    for (int i = t; i < C * C; i += 256) Ws[(i / C) * 87 + (i % C)] = Wv[i];
    __syncthreads();
    // M = P Wv -> bf16 hi/lo, zero-padded to 96x96
    for (int i = t; i < 96 * 96; i += 256) {
        const int r = i / 96, f = i % 96;
        float a = 0.f;
        if (r < C && f < C)
            for (int e = 0; e < C; e++) a += Gs[r * 86 + e] * Ws[e * 87 + f];
        const __nv_bfloat16 h = __float2bfloat16(a);
        g_Mhi[b][i] = h;
        g_Mlo[b][i] = __float2bfloat16(a - __bfloat162float(h));
    }
}

// ============ kernel 3: out = M X + c 1^T via HMMA (3-product bf16 emulation) ============
// grid (64 L-tiles of 128, NB), 256 thr, warp grid 2(M) x 4(N), warp tile 48x32
__global__ __launch_bounds__(256, 2) void k_out(const float* __restrict__ x,
                                                float* __restrict__ out) {
    extern __shared__ __align__(128) uint8_t dsm[];
    uint8_t* sMhi = dsm;             // 96 rows x 256B (192B data + swizzle pad)
    uint8_t* sMlo = dsm + 24576;
    uint8_t* sXhi = dsm + 49152;     // 96 k-rows x 256B (128 n bf16)
    uint8_t* sXlo = dsm + 73728;
    const int b = blockIdx.y, tile = blockIdx.x;
    const int t = threadIdx.x, lane = t & 31, wid = t >> 5;
    const uint32_t uMhi = smem_u32(sMhi), uMlo = smem_u32(sMlo);
    const uint32_t uXhi = smem_u32(sXhi), uXlo = smem_u32(sXlo);

    // stage M (already bf16-split, swizzled copy)
    for (int ci = t; ci < 1152; ci += 256) {
        const int r = ci / 12;
        const uint32_t cb = (uint32_t)((ci % 12) * 16);
        const uint32_t sw = cb ^ ((r & 7) << 4);
        *(uint4*)(sMhi + r * 256 + sw) = *(const uint4*)((const uint8_t*)g_Mhi[b] + ci * 16);
        *(uint4*)(sMlo + r * 256 + sw) = *(const uint4*)((const uint8_t*)g_Mlo[b] + ci * 16);
    }
    // stage X tile: k-rows 0..95 (>=85 zeroed), 128 n fp32 -> bf16 hi/lo
    const float* xb = x + (size_t)b * C * SEQ + tile * 128;
#pragma unroll
    for (int i = 0; i < 12; i++) {
        const int r = wid + 8 * i;
        const uint32_t cb = (uint32_t)(lane * 8) ^ ((r & 7) << 4);
        uint2 hv = make_uint2(0u, 0u), lv = make_uint2(0u, 0u);
        if (r < C) {
            const float4 w = *(const float4*)(xb + (size_t)r * SEQ + lane * 4);
            __nv_bfloat162 h01 = __floats2bfloat162_rn(w.x, w.y);
            __nv_bfloat162 h23 = __floats2bfloat162_rn(w.z, w.w);
            float2 f01 = __bfloat1622float2(h01);
            float2 f23 = __bfloat1622float2(h23);
            __nv_bfloat162 l01 = __floats2bfloat162_rn(w.x - f01.x, w.y - f01.y);
            __nv_bfloat162 l23 = __floats2bfloat162_rn(w.z - f23.x, w.w - f23.y);
            hv = make_uint2(*(uint32_t*)&h01, *(uint32_t*)&h23);
            lv = make_uint2(*(uint32_t*)&l01, *(uint32_t*)&l23);
        }
        *(uint2*)(sXhi + r * 256 + cb) = hv;
        *(uint2*)(sXlo + r * 256 + cb) = lv;
    }
    __syncthreads();

    const int wr = wid >> 2, wc = wid & 3;
    const int m0 = wr * 48, n0 = wc * 32;
    float acc[3][4][4];
#pragma unroll
    for (int mt = 0; mt < 3; mt++)
#pragma unroll
        for (int nt = 0; nt < 4; nt++)
#pragma unroll
            for (int e = 0; e < 4; e++) acc[mt][nt][e] = 0.f;

#pragma unroll
    for (int k = 0; k < 6; ++k) {
        uint32_t ahi[3][4], alo[3][4], bhi[2][4], blo[2][4];
        const uint32_t cbA = 32 * k + ((lane & 16) ? 16 : 0);
#pragma unroll
        for (int mt = 0; mt < 3; mt++) {
            const int row = m0 + mt * 16 + (lane & 15);
            const uint32_t sw = cbA ^ ((row & 7) << 4);
            ldsm4(ahi[mt][0], ahi[mt][1], ahi[mt][2], ahi[mt][3], uMhi + row * 256 + sw);
            ldsm4(alo[mt][0], alo[mt][1], alo[mt][2], alo[mt][3], uMlo + row * 256 + sw);
        }
        const int rowB = 16 * k + (lane & 7) + ((lane & 8) ? 8 : 0);
#pragma unroll
        for (int np = 0; np < 2; np++) {
            const uint32_t cbn = (uint32_t)(n0 * 2 + np * 32 + ((lane & 16) ? 16 : 0));
            const uint32_t sw = cbn ^ ((rowB & 7) << 4);
            ldsm4t(bhi[np][0], bhi[np][1], bhi[np][2], bhi[np][3], uXhi + rowB * 256 + sw);
            ldsm4t(blo[np][0], blo[np][1], blo[np][2], blo[np][3], uXlo + rowB * 256 + sw);
        }
#pragma unroll
        for (int mt = 0; mt < 3; mt++)
#pragma unroll
            for (int nt = 0; nt < 4; nt++) {
                const int np = nt >> 1;
                const uint32_t bh0 = (nt & 1) ? bhi[np][2] : bhi[np][0];
                const uint32_t bh1 = (nt & 1) ? bhi[np][3] : bhi[np][1];
                const uint32_t bl0 = (nt & 1) ? blo[np][2] : blo[np][0];
                const uint32_t bl1 = (nt & 1) ? blo[np][3] : blo[np][1];
                mma_bf16(acc[mt][nt], ahi[mt], bh0, bh1);
                mma_bf16(acc[mt][nt], ahi[mt], bl0, bl1);
                mma_bf16(acc[mt][nt], alo[mt], bh0, bh1);
            }
    }

#pragma unroll
    for (int mt = 0; mt < 3; mt++) {
        const int row = m0 + mt * 16 + (lane >> 2);
        const float c0 = (row < C) ? g_c[b][row] : 0.f;
        const float c1 = (row + 8 < C) ? g_c[b][row + 8] : 0.f;
#pragma unroll
        for (int nt = 0; nt < 4; nt++) {
            const int col = tile * 128 + n0 + nt * 8 + (lane & 3) * 2;
            if (row < C)
                *(float2*)(out + (size_t)b * C * SEQ + (size_t)row * SEQ + col) =
                    make_float2(acc[mt][nt][0] + c0, acc[mt][nt][1] + c0);
            if (row + 8 < C)
                *(float2*)(out + (size_t)b * C * SEQ + (size_t)(row + 8) * SEQ + col) =
                    make_float2(acc[mt][nt][2] + c1, acc[mt][nt][3] + c1);
        }
    }
}

extern "C" void kernel_launch(void* const* d_in, const int* in_sizes, int n_in,
                              void* d_out, int out_size) {
    const float* x  = (const float*)d_in[0];
    const float* Wq = (const float*)d_in[1];
    const float* bq = (const float*)d_in[2];
    const float* Wk = (const float*)d_in[3];
    const float* bk = (const float*)d_in[4];
    const float* Wv = (const float*)d_in[5];
    const float* bv = (const float*)d_in[6];
    float* out = (float*)d_out;

    static bool attr_done = false;
    if (!attr_done) {
        cudaFuncSetAttribute(k_mid, cudaFuncAttributeMaxDynamicSharedMemorySize, 90112);
        cudaFuncSetAttribute(k_out, cudaFuncAttributeMaxDynamicSharedMemorySize, 98304);
        attr_done = true;
    }

    k_gram<<<dim3(KCHK, NB), 256>>>(x);
    k_mid<<<NB, 256, 22015 * sizeof(float)>>>(Wq, Wk, Wv, bq, bk, bv);
    k_out<<<dim3(64, NB), 256, 98304>>>(x, out);
}